// round 7
// baseline (speedup 1.0000x reference)
#include <cuda_runtime.h>
#include <math.h>

// GRU: B=128, T=512, I=256, H=512. out = final h [1,128,512] fp32.
// Persistent kernel, 128 CTAs (4 batch-chunks x 32 j-slices), weights in SMEM.
// 512 threads/CTA, K split 8-way across lanes, thread tile 2j x 4b x 3 gates
// (R2's 1.67 B/MAC traffic at R3's occupancy). Overlapped split grid barrier.

#define BATCH 128
#define TT    512
#define II    256
#define HH    512
#define GB    4
#define GJ    32
#define BC    32
#define JC    16
#define NCTA  (GB*GJ)
#define NTHR  512
#define USTRIDE 260          // multiple of 4 floats; 128B segments stay conflict-free
#define WSTRIDE 772

#define SMEM_W   (48*WSTRIDE)
#define SMEM_U   (32*USTRIDE)
#define SMEM_FLOATS (SMEM_W + 2*SMEM_U + 64)
#define SMEM_BYTES  (SMEM_FLOATS*4)

typedef unsigned long long ull;

__device__ float g_h[2][BATCH*HH];
__device__ unsigned int g_count = 0;
__device__ unsigned int g_phase = 0;

__device__ __forceinline__ void fma2(ull &d, ull a, ull b) {
    asm("fma.rn.f32x2 %0, %1, %2, %0;" : "+l"(d) : "l"(a), "l"(b));
}
__device__ __forceinline__ float foldadd(ull v) {
    float lo, hi;
    asm("mov.b64 {%0, %1}, %2;" : "=f"(lo), "=f"(hi) : "l"(v));
    return lo + hi;
}
__device__ __forceinline__ float red8(float v) {
    v += __shfl_xor_sync(0xFFFFFFFFu, v, 1);
    v += __shfl_xor_sync(0xFFFFFFFFu, v, 2);
    v += __shfl_xor_sync(0xFFFFFFFFu, v, 4);
    return v;
}
__device__ __forceinline__ float sigm(float x) {
    return 1.0f / (1.0f + __expf(-x));
}

__device__ __forceinline__ void grid_sync_full() {
    __syncthreads();
    if (threadIdx.x == 0) {
        __threadfence();
        unsigned gen = *((volatile unsigned*)&g_phase);
        if (atomicAdd(&g_count, 1u) == NCTA - 1u) {
            g_count = 0;
            __threadfence();
            *((volatile unsigned*)&g_phase) = gen + 1u;
        } else {
            while (*((volatile unsigned*)&g_phase) == gen) { __nanosleep(32); }
        }
        __threadfence();
    }
    __syncthreads();
}

extern "C" __global__ void __launch_bounds__(NTHR, 1)
gru_persistent_kernel(const float* __restrict__ x,      // [B, T, I]
                      const float* __restrict__ W_ih,   // [3H, I]
                      const float* __restrict__ W_hh,   // [3H, H]
                      const float* __restrict__ b_ih,   // [3H]
                      const float* __restrict__ b_hh,   // [3H]
                      float* __restrict__ out)          // [1, B, H]
{
    extern __shared__ float smem[];
    float* W_s  = smem;                 // [48][WSTRIDE] fused [W_ih | W_hh]
    float* U_s0 = W_s + SMEM_W;         // [32][USTRIDE]  (x chunk / h[256:512])
    float* U_s1 = U_s0 + SMEM_U;        // [32][USTRIDE]  (h[0:256])
    float* B_s  = U_s1 + SMEM_U;        // [64]

    const int tid = threadIdx.x;
    const int bx  = blockIdx.x;
    const int gb  = bx & (GB - 1);
    const int gj  = bx >> 2;
    const int b0  = gb * BC;
    const int j0  = gj * JC;

    // ---- one-time: weight tile into SMEM (rows 0-15 r, 16-31 z, 32-47 n) ----
    for (int idx = tid; idx < 48 * 768; idx += NTHR) {
        int row = idx / 768;
        int col = idx - row * 768;
        int G;
        if (row < 16)      G = j0 + row;
        else if (row < 32) G = 512 + j0 + (row - 16);
        else               G = 1024 + j0 + (row - 32);
        float v = (col < II) ? W_ih[G * II + col] : W_hh[G * HH + (col - II)];
        W_s[row * WSTRIDE + col] = v;
    }
    if (tid < 64) {
        int i = tid & 15;
        float v;
        if (tid < 16)      v = b_ih[j0 + i]       + b_hh[j0 + i];        // r
        else if (tid < 32) v = b_ih[512 + j0 + i] + b_hh[512 + j0 + i];  // z
        else if (tid < 48) v = b_ih[1024 + j0 + i];                      // xn
        else               v = b_hh[1024 + j0 + i];                      // hn
        B_s[tid] = v;
    }

    // zero h0, stage x(t=0) into buf0
    for (int idx = bx * NTHR + tid; idx < BATCH * HH; idx += NCTA * NTHR)
        g_h[0][idx] = 0.0f;

    const int ldrow = tid >> 4;          // 0..31
    const int ldv   = tid & 15;          // 0..15
    {
        const float4* xsrc = (const float4*)(x + ((size_t)(b0 + ldrow) * TT) * II);
        float4* dx = (float4*)(U_s0 + ldrow * USTRIDE);
        #pragma unroll
        for (int it = 0; it < 4; it++)
            dx[ldv + 16 * it] = xsrc[ldv + 16 * it];
    }

    grid_sync_full();   // phase -> 1; h0 + x(0) visible

    // thread mapping: s = k-slice (8-way), bslot = batch base, jp = j pair
    const int s     = tid & 7;           // k-slice lane (warp bits 0-2)
    const int bslot = (tid >> 3) & 7;    // batch rows: bslot + {0,8,16,24}
    const int jp    = tid >> 6;          // 0..7

    const float br_[2]  = { B_s[2*jp],      B_s[2*jp + 1] };
    const float bz_[2]  = { B_s[16 + 2*jp], B_s[16 + 2*jp + 1] };
    const float bxn_[2] = { B_s[32 + 2*jp], B_s[32 + 2*jp + 1] };
    const float bhn_[2] = { B_s[48 + 2*jp], B_s[48 + 2*jp + 1] };

    // W row pointers in ulonglong2 units, k-slice s baked in.
    // Per iter i, lane reads element [8*i]; the 8 s-lanes cover 128B contiguous.
    const ulonglong2* wR0 = (const ulonglong2*)(W_s + (2*jp+0)*WSTRIDE) + s;
    const ulonglong2* wR1 = (const ulonglong2*)(W_s + (2*jp+1)*WSTRIDE) + s;
    const ulonglong2* wZ0 = (const ulonglong2*)(W_s + (16+2*jp+0)*WSTRIDE) + s;
    const ulonglong2* wZ1 = (const ulonglong2*)(W_s + (16+2*jp+1)*WSTRIDE) + s;
    const ulonglong2* wN0 = (const ulonglong2*)(W_s + (32+2*jp+0)*WSTRIDE) + s;
    const ulonglong2* wN1 = (const ulonglong2*)(W_s + (32+2*jp+1)*WSTRIDE) + s;

    const ulonglong2* uq0_b0 = (const ulonglong2*)(U_s0 + (bslot+ 0)*USTRIDE) + s;
    const ulonglong2* uq1_b0 = (const ulonglong2*)(U_s0 + (bslot+ 8)*USTRIDE) + s;
    const ulonglong2* uq2_b0 = (const ulonglong2*)(U_s0 + (bslot+16)*USTRIDE) + s;
    const ulonglong2* uq3_b0 = (const ulonglong2*)(U_s0 + (bslot+24)*USTRIDE) + s;
    const ulonglong2* uq0_b1 = (const ulonglong2*)(U_s1 + (bslot+ 0)*USTRIDE) + s;
    const ulonglong2* uq1_b1 = (const ulonglong2*)(U_s1 + (bslot+ 8)*USTRIDE) + s;
    const ulonglong2* uq2_b1 = (const ulonglong2*)(U_s1 + (bslot+16)*USTRIDE) + s;
    const ulonglong2* uq3_b1 = (const ulonglong2*)(U_s1 + (bslot+24)*USTRIDE) + s;

    for (int t = 0; t < TT; t++) {
        const int rp = t & 1;
        const int wp = rp ^ 1;

        ull ar[2][4], az[2][4], an[2][4];
        float xn[2][4];
        #pragma unroll
        for (int jj = 0; jj < 2; jj++)
            #pragma unroll
            for (int q = 0; q < 4; q++) { ar[jj][q] = 0; az[jj][q] = 0; an[jj][q] = 0; }

        // ======== chunk 0: x gates from buf0 (independent of peers' h) ========
        {
            #pragma unroll 2
            for (int i = 0; i < 8; i++) {
                const int idx = 8 * i;
                ulonglong2 Ua = uq0_b0[idx];
                ulonglong2 Ub = uq1_b0[idx];
                ulonglong2 Uc = uq2_b0[idx];
                ulonglong2 Ud = uq3_b0[idx];
                ulonglong2 R0 = wR0[idx], R1 = wR1[idx];
                ulonglong2 Z0 = wZ0[idx], Z1 = wZ1[idx];
                ulonglong2 N0 = wN0[idx], N1 = wN1[idx];
                fma2(ar[0][0], R0.x, Ua.x); fma2(ar[0][0], R0.y, Ua.y);
                fma2(ar[0][1], R0.x, Ub.x); fma2(ar[0][1], R0.y, Ub.y);
                fma2(ar[0][2], R0.x, Uc.x); fma2(ar[0][2], R0.y, Uc.y);
                fma2(ar[0][3], R0.x, Ud.x); fma2(ar[0][3], R0.y, Ud.y);
                fma2(ar[1][0], R1.x, Ua.x); fma2(ar[1][0], R1.y, Ua.y);
                fma2(ar[1][1], R1.x, Ub.x); fma2(ar[1][1], R1.y, Ub.y);
                fma2(ar[1][2], R1.x, Uc.x); fma2(ar[1][2], R1.y, Uc.y);
                fma2(ar[1][3], R1.x, Ud.x); fma2(ar[1][3], R1.y, Ud.y);
                fma2(az[0][0], Z0.x, Ua.x); fma2(az[0][0], Z0.y, Ua.y);
                fma2(az[0][1], Z0.x, Ub.x); fma2(az[0][1], Z0.y, Ub.y);
                fma2(az[0][2], Z0.x, Uc.x); fma2(az[0][2], Z0.y, Uc.y);
                fma2(az[0][3], Z0.x, Ud.x); fma2(az[0][3], Z0.y, Ud.y);
                fma2(az[1][0], Z1.x, Ua.x); fma2(az[1][0], Z1.y, Ua.y);
                fma2(az[1][1], Z1.x, Ub.x); fma2(az[1][1], Z1.y, Ub.y);
                fma2(az[1][2], Z1.x, Uc.x); fma2(az[1][2], Z1.y, Uc.y);
                fma2(az[1][3], Z1.x, Ud.x); fma2(az[1][3], Z1.y, Ud.y);
                fma2(an[0][0], N0.x, Ua.x); fma2(an[0][0], N0.y, Ua.y);
                fma2(an[0][1], N0.x, Ub.x); fma2(an[0][1], N0.y, Ub.y);
                fma2(an[0][2], N0.x, Uc.x); fma2(an[0][2], N0.y, Uc.y);
                fma2(an[0][3], N0.x, Ud.x); fma2(an[0][3], N0.y, Ud.y);
                fma2(an[1][0], N1.x, Ua.x); fma2(an[1][0], N1.y, Ua.y);
                fma2(an[1][1], N1.x, Ub.x); fma2(an[1][1], N1.y, Ub.y);
                fma2(an[1][2], N1.x, Uc.x); fma2(an[1][2], N1.y, Uc.y);
                fma2(an[1][3], N1.x, Ud.x); fma2(an[1][3], N1.y, Ud.y);
            }
        }
        #pragma unroll
        for (int jj = 0; jj < 2; jj++)
            #pragma unroll
            for (int q = 0; q < 4; q++) { xn[jj][q] = foldadd(an[jj][q]); an[jj][q] = 0; }

        // ---- wait for peers' h(t-1) (hidden behind chunk-0 compute) ----
        if (tid == 0) {
            while (*((volatile unsigned*)&g_phase) < (unsigned)(t + 1)) { __nanosleep(32); }
            __threadfence();
        }
        __syncthreads();

        // ---- stage h: h[0:256] -> buf1, h[256:512] -> buf0 ----
        {
            const float4* hsrc = (const float4*)(g_h[rp] + (b0 + ldrow) * HH);
            float4* d1 = (float4*)(U_s1 + ldrow * USTRIDE);
            float4* d0 = (float4*)(U_s0 + ldrow * USTRIDE);
            #pragma unroll
            for (int it = 0; it < 4; it++) d1[ldv + 16*it] = hsrc[ldv + 16*it];
            #pragma unroll
            for (int it = 0; it < 4; it++) d0[ldv + 16*it] = hsrc[64 + ldv + 16*it];
        }
        __syncthreads();

        // ======== chunks 1 (buf1) + 2 (buf0): h gates ========
        #pragma unroll
        for (int c = 1; c < 3; c++) {
            const ulonglong2* pR0 = wR0 + c*64, * pR1 = wR1 + c*64;
            const ulonglong2* pZ0 = wZ0 + c*64, * pZ1 = wZ1 + c*64;
            const ulonglong2* pN0 = wN0 + c*64, * pN1 = wN1 + c*64;
            const ulonglong2* pu0 = (c == 1) ? uq0_b1 : uq0_b0;
            const ulonglong2* pu1 = (c == 1) ? uq1_b1 : uq1_b0;
            const ulonglong2* pu2 = (c == 1) ? uq2_b1 : uq2_b0;
            const ulonglong2* pu3 = (c == 1) ? uq3_b1 : uq3_b0;
            #pragma unroll 2
            for (int i = 0; i < 8; i++) {
                const int idx = 8 * i;
                ulonglong2 Ua = pu0[idx];
                ulonglong2 Ub = pu1[idx];
                ulonglong2 Uc = pu2[idx];
                ulonglong2 Ud = pu3[idx];
                ulonglong2 R0 = pR0[idx], R1 = pR1[idx];
                ulonglong2 Z0 = pZ0[idx], Z1 = pZ1[idx];
                ulonglong2 N0 = pN0[idx], N1 = pN1[idx];
                fma2(ar[0][0], R0.x, Ua.x); fma2(ar[0][0], R0.y, Ua.y);
                fma2(ar[0][1], R0.x, Ub.x); fma2(ar[0][1], R0.y, Ub.y);
                fma2(ar[0][2], R0.x, Uc.x); fma2(ar[0][2], R0.y, Uc.y);
                fma2(ar[0][3], R0.x, Ud.x); fma2(ar[0][3], R0.y, Ud.y);
                fma2(ar[1][0], R1.x, Ua.x); fma2(ar[1][0], R1.y, Ua.y);
                fma2(ar[1][1], R1.x, Ub.x); fma2(ar[1][1], R1.y, Ub.y);
                fma2(ar[1][2], R1.x, Uc.x); fma2(ar[1][2], R1.y, Uc.y);
                fma2(ar[1][3], R1.x, Ud.x); fma2(ar[1][3], R1.y, Ud.y);
                fma2(az[0][0], Z0.x, Ua.x); fma2(az[0][0], Z0.y, Ua.y);
                fma2(az[0][1], Z0.x, Ub.x); fma2(az[0][1], Z0.y, Ub.y);
                fma2(az[0][2], Z0.x, Uc.x); fma2(az[0][2], Z0.y, Uc.y);
                fma2(az[0][3], Z0.x, Ud.x); fma2(az[0][3], Z0.y, Ud.y);
                fma2(az[1][0], Z1.x, Ua.x); fma2(az[1][0], Z1.y, Ua.y);
                fma2(az[1][1], Z1.x, Ub.x); fma2(az[1][1], Z1.y, Ub.y);
                fma2(az[1][2], Z1.x, Uc.x); fma2(az[1][2], Z1.y, Uc.y);
                fma2(az[1][3], Z1.x, Ud.x); fma2(az[1][3], Z1.y, Ud.y);
                fma2(an[0][0], N0.x, Ua.x); fma2(an[0][0], N0.y, Ua.y);
                fma2(an[0][1], N0.x, Ub.x); fma2(an[0][1], N0.y, Ub.y);
                fma2(an[0][2], N0.x, Uc.x); fma2(an[0][2], N0.y, Uc.y);
                fma2(an[0][3], N0.x, Ud.x); fma2(an[0][3], N0.y, Ud.y);
                fma2(an[1][0], N1.x, Ua.x); fma2(an[1][0], N1.y, Ua.y);
                fma2(an[1][1], N1.x, Ub.x); fma2(an[1][1], N1.y, Ub.y);
                fma2(an[1][2], N1.x, Uc.x); fma2(an[1][2], N1.y, Uc.y);
                fma2(an[1][3], N1.x, Ud.x); fma2(an[1][3], N1.y, Ud.y);
            }
        }

        // ---- reduce across 8 k-slice lanes + gates + h update ----
        float vr[2][4], vz[2][4], vh[2][4];
        #pragma unroll
        for (int jj = 0; jj < 2; jj++)
            #pragma unroll
            for (int q = 0; q < 4; q++) {
                vr[jj][q] = red8(foldadd(ar[jj][q]));
                vz[jj][q] = red8(foldadd(az[jj][q]));
                vh[jj][q] = red8(foldadd(an[jj][q]));
                xn[jj][q] = red8(xn[jj][q]);
            }

        if (s == 0) {
            #pragma unroll
            for (int q = 0; q < 4; q++) {
                const int b_local = bslot + 8 * q;
                const int bg = b0 + b_local;
                float2 hnew;
                #pragma unroll
                for (int jj = 0; jj < 2; jj++) {
                    const int j = j0 + 2 * jp + jj;
                    float r = sigm(vr[jj][q] + br_[jj]);
                    float z = sigm(vz[jj][q] + bz_[jj]);
                    float n = tanhf(xn[jj][q] + bxn_[jj] + r * (vh[jj][q] + bhn_[jj]));
                    const float* hbuf = (j < 256) ? U_s1 : U_s0;
                    float hold = hbuf[b_local * USTRIDE + (j & 255)];
                    float hv = n + z * (hold - n);
                    if (jj == 0) hnew.x = hv; else hnew.y = hv;
                }
                *(float2*)(g_h[wp] + bg * HH + j0 + 2 * jp) = hnew;
                if (t == TT - 1)
                    *(float2*)(out + bg * HH + j0 + 2 * jp) = hnew;
            }
        }

        __syncthreads();   // all h writes + all buf reads done

        // ---- arrive (peers proceed once all CTAs hit this point) ----
        if (tid == 0) {
            __threadfence();
            if (atomicAdd(&g_count, 1u) == NCTA - 1u) {
                g_count = 0;
                __threadfence();
                *((volatile unsigned*)&g_phase) = (unsigned)(t + 2);
            }
        }

        // ---- stage x(t+1) into buf0 (independent of peers) ----
        if (t < TT - 1) {
            const float4* xsrc = (const float4*)(x + ((size_t)(b0 + ldrow) * TT + (t + 1)) * II);
            float4* dx = (float4*)(U_s0 + ldrow * USTRIDE);
            #pragma unroll
            for (int it = 0; it < 4; it++)
                dx[ldv + 16 * it] = xsrc[ldv + 16 * it];
        }
        __syncthreads();
    }
}

extern "C" void kernel_launch(void* const* d_in, const int* in_sizes, int n_in,
                              void* d_out, int out_size) {
    (void)in_sizes; (void)n_in; (void)out_size;
    cudaFuncSetAttribute(gru_persistent_kernel,
                         cudaFuncAttributeMaxDynamicSharedMemorySize, SMEM_BYTES);
    gru_persistent_kernel<<<NCTA, NTHR, SMEM_BYTES>>>(
        (const float*)d_in[0],
        (const float*)d_in[1],
        (const float*)d_in[2],
        (const float*)d_in[3],
        (const float*)d_in[4],
        (float*)d_out);
}

// round 8
// speedup vs baseline: 2.0422x; 2.0422x over previous
#include <cuda_runtime.h>
#include <cuda_bf16.h>
#include <mma.h>
#include <math.h>

// GRU: B=128, T=512, I=256, H=512. out = final h [1,128,512] fp32.
// Persistent kernel, 128 CTAs (4 batch x 32 j slices), wmma bf16 hi/lo split
// (3-product ~fp32 emulation) on tensor cores. W resident in SMEM as bf16
// hi/lo; h kept in gmem as fp32 + packed (bf16hi,bf16lo) u32; x pre-packed.

using namespace nvcuda;

#define BATCH 128
#define TT    512
#define II    256
#define HH    512
#define GB    4
#define GJ    32
#define BC    32
#define JC    16
#define NCTA  (GB*GJ)
#define NTHR  512

#define WSTRIDE 776     // bf16 elems per W row (768 + 8)
#define USTRIDE 264     // bf16 elems per U row (256 + 8)

// SMEM byte offsets
#define SM_WH   0
#define SM_WL   (SM_WH  + 48*WSTRIDE*2)        // 74496
#define SM_UH1  (SM_WL  + 48*WSTRIDE*2)        // 148992   buf1 = h[0:256]
#define SM_UL1  (SM_UH1 + 32*USTRIDE*2)        // +16896
#define SM_UH0  (SM_UL1 + 32*USTRIDE*2)        // buf0 = x / h[256:512]
#define SM_UL0  (SM_UH0 + 32*USTRIDE*2)
#define SM_DRED (SM_UL0 + 32*USTRIDE*2)        // 6 tiles * 256 f32
#define SM_DXN  (SM_DRED + 6*256*4)            // 4 tiles * 256 f32
#define SM_BS   (SM_DXN + 4*256*4)             // 64 f32
#define SMEM_BYTES (SM_BS + 256)               // 227072

__device__ float        g_h [2][BATCH*HH];
__device__ unsigned int g_hs[2][BATCH*HH];                 // packed (hi<<16)|lo
__device__ unsigned int g_xs[(size_t)BATCH*TT*II];         // packed x
__device__ unsigned int g_count = 0;
__device__ unsigned int g_phase = 0;

__device__ __forceinline__ float sigm(float x) {
    return 1.0f / (1.0f + __expf(-x));
}
__device__ __forceinline__ unsigned pack_bf16x2(float v) {
    __nv_bfloat16 hi = __float2bfloat16(v);
    float hif = __bfloat162float(hi);
    __nv_bfloat16 lo = __float2bfloat16(v - hif);
    return ((unsigned)__bfloat16_as_ushort(hi) << 16) |
           (unsigned)__bfloat16_as_ushort(lo);
}

__device__ __forceinline__ void grid_sync_full() {
    __syncthreads();
    if (threadIdx.x == 0) {
        __threadfence();
        unsigned gen = *((volatile unsigned*)&g_phase);
        if (atomicAdd(&g_count, 1u) == NCTA - 1u) {
            g_count = 0;
            __threadfence();
            *((volatile unsigned*)&g_phase) = gen + 1u;
        } else {
            while (*((volatile unsigned*)&g_phase) == gen) { __nanosleep(32); }
        }
        __threadfence();
    }
    __syncthreads();
}

extern "C" __global__ void __launch_bounds__(NTHR, 1)
gru_persistent_kernel(const float* __restrict__ x,      // [B, T, I]
                      const float* __restrict__ W_ih,   // [3H, I]
                      const float* __restrict__ W_hh,   // [3H, H]
                      const float* __restrict__ b_ih,   // [3H]
                      const float* __restrict__ b_hh,   // [3H]
                      float* __restrict__ out)          // [1, B, H]
{
    extern __shared__ char smem[];
    unsigned short* Wh  = (unsigned short*)(smem + SM_WH);
    unsigned short* Wl  = (unsigned short*)(smem + SM_WL);
    unsigned short* Uh1 = (unsigned short*)(smem + SM_UH1);
    unsigned short* Ul1 = (unsigned short*)(smem + SM_UL1);
    unsigned short* Uh0 = (unsigned short*)(smem + SM_UH0);
    unsigned short* Ul0 = (unsigned short*)(smem + SM_UL0);
    float* Dred = (float*)(smem + SM_DRED);
    float* Dxn  = (float*)(smem + SM_DXN);
    float* B_s  = (float*)(smem + SM_BS);

    const int tid = threadIdx.x;
    const int bx  = blockIdx.x;
    const int gb  = bx & (GB - 1);
    const int gj  = bx >> 2;
    const int b0  = gb * BC;
    const int j0  = gj * JC;

    // relative-phase base (read BEFORE init barrier; flip happens after all reads)
    unsigned base = 0;
    if (tid == 0) base = *((volatile unsigned*)&g_phase);

    // ---- one-time: W tile as bf16 hi/lo (rows 0-15 r, 16-31 z, 32-47 n) ----
    for (int idx = tid; idx < 48 * 768; idx += NTHR) {
        int row = idx / 768;
        int col = idx - row * 768;
        int G;
        if (row < 16)      G = j0 + row;
        else if (row < 32) G = 512 + j0 + (row - 16);
        else               G = 1024 + j0 + (row - 32);
        float v = (col < II) ? W_ih[G * II + col] : W_hh[G * HH + (col - II)];
        __nv_bfloat16 hi = __float2bfloat16(v);
        __nv_bfloat16 lo = __float2bfloat16(v - __bfloat162float(hi));
        Wh[row * WSTRIDE + col] = __bfloat16_as_ushort(hi);
        Wl[row * WSTRIDE + col] = __bfloat16_as_ushort(lo);
    }
    if (tid < 64) {
        int i = tid & 15;
        float v;
        if (tid < 16)      v = b_ih[j0 + i]       + b_hh[j0 + i];        // r
        else if (tid < 32) v = b_ih[512 + j0 + i] + b_hh[512 + j0 + i];  // z
        else if (tid < 48) v = b_ih[1024 + j0 + i];                      // xn
        else               v = b_hh[1024 + j0 + i];                      // hn
        B_s[tid] = v;
    }

    // ---- pre-phase: pack all x into g_xs; zero h0 ----
    {
        const float4* x4 = (const float4*)x;
        uint4* xs4 = (uint4*)g_xs;
        const int total4 = BATCH * TT * II / 4;
        for (int i = bx * NTHR + tid; i < total4; i += NCTA * NTHR) {
            float4 v = x4[i];
            uint4 p;
            p.x = pack_bf16x2(v.x); p.y = pack_bf16x2(v.y);
            p.z = pack_bf16x2(v.z); p.w = pack_bf16x2(v.w);
            xs4[i] = p;
        }
        for (int i = bx * NTHR + tid; i < BATCH * HH; i += NCTA * NTHR) {
            g_h[0][i] = 0.0f;
            g_hs[0][i] = 0u;
        }
    }

    grid_sync_full();   // phase -> base+1

    // warp roles: w<12 do mma. tau = w>>1 in 0..5, kh = w&1.
    const int w   = tid >> 5;
    const int kh  = w & 1;
    const int tau = w >> 1;
    const int btile = tau / 3;
    const int ntile = tau % 3;

    wmma::fragment<wmma::matrix_a, 16, 16, 16, __nv_bfloat16, wmma::row_major> fa_h, fa_l;
    wmma::fragment<wmma::matrix_b, 16, 16, 16, __nv_bfloat16, wmma::col_major> fb_h, fb_l;
    wmma::fragment<wmma::accumulator, 16, 16, 16, float> facc, fc2;

    // staging indices
    const int srow = tid >> 4;          // 0..31
    const int sk16 = (tid & 15) * 16;   // x staging: 16 elems
    const int sk32 = (tid & 15) * 32;   // h staging: 32 elems

    // gate-stage mapping
    const int jj = tid & 15;
    const int bb = tid >> 4;            // 0..31
    const int gbt = bb >> 4;
    const int gbl = bb & 15;
    const float bias_r  = B_s[jj];
    const float bias_z  = B_s[16 + jj];
    const float bias_xn = B_s[32 + jj];
    const float bias_hn = B_s[48 + jj];

    for (int t = 0; t < TT; t++) {
        const int rp = t & 1;
        const int wp = rp ^ 1;

        // ---- stage x(t) (packed) into buf0 ----
        {
            const uint4* src = (const uint4*)(g_xs + ((size_t)(b0 + srow) * TT + t) * II + sk16);
            unsigned short* dh = Uh0 + srow * USTRIDE + sk16;
            unsigned short* dl = Ul0 + srow * USTRIDE + sk16;
            #pragma unroll
            for (int v4 = 0; v4 < 4; v4++) {
                uint4 u = src[v4];
                dh[v4*4+0] = (unsigned short)(u.x >> 16); dl[v4*4+0] = (unsigned short)u.x;
                dh[v4*4+1] = (unsigned short)(u.y >> 16); dl[v4*4+1] = (unsigned short)u.y;
                dh[v4*4+2] = (unsigned short)(u.z >> 16); dl[v4*4+2] = (unsigned short)u.z;
                dh[v4*4+3] = (unsigned short)(u.w >> 16); dl[v4*4+3] = (unsigned short)u.w;
            }
        }
        __syncthreads();

        // ---- chunk 0: x projection (independent of peers' h) ----
        if (w < 12) {
            wmma::fill_fragment(facc, 0.0f);
            const __nv_bfloat16* Ah = (const __nv_bfloat16*)(Uh0 + btile * 16 * USTRIDE);
            const __nv_bfloat16* Al = (const __nv_bfloat16*)(Ul0 + btile * 16 * USTRIDE);
            const __nv_bfloat16* Bh = (const __nv_bfloat16*)(Wh + ntile * 16 * WSTRIDE);
            const __nv_bfloat16* Bl = (const __nv_bfloat16*)(Wl + ntile * 16 * WSTRIDE);
            #pragma unroll
            for (int ks = kh * 8; ks < kh * 8 + 8; ks++) {
                wmma::load_matrix_sync(fa_h, Ah + ks * 16, USTRIDE);
                wmma::load_matrix_sync(fa_l, Al + ks * 16, USTRIDE);
                wmma::load_matrix_sync(fb_h, Bh + ks * 16, WSTRIDE);
                wmma::load_matrix_sync(fb_l, Bl + ks * 16, WSTRIDE);
                wmma::mma_sync(facc, fa_h, fb_h, facc);
                wmma::mma_sync(facc, fa_h, fb_l, facc);
                wmma::mma_sync(facc, fa_l, fb_h, facc);
            }
            if (ntile == 2) {   // n-gate: keep x-part separate, reset accumulator
                wmma::store_matrix_sync(Dxn + (btile * 2 + kh) * 256, facc, 16, wmma::mem_row_major);
                wmma::fill_fragment(facc, 0.0f);
            }
        }

        // ---- wait for peers' h(t-1) (overlapped by x staging + chunk-0 mma) ----
        if (tid == 0) {
            while ((unsigned)(*((volatile unsigned*)&g_phase) - base) < (unsigned)(t + 1)) {
                __nanosleep(32);
            }
            __threadfence();
        }
        __syncthreads();

        // ---- stage h (packed): h[0:256]->buf1, h[256:512]->buf0 ----
        {
            const uint4* src = (const uint4*)(g_hs[rp] + (b0 + srow) * HH + sk32);
            unsigned short *dh, *dl;
            if (sk32 < 256) {
                dh = Uh1 + srow * USTRIDE + sk32;
                dl = Ul1 + srow * USTRIDE + sk32;
            } else {
                dh = Uh0 + srow * USTRIDE + (sk32 - 256);
                dl = Ul0 + srow * USTRIDE + (sk32 - 256);
            }
            #pragma unroll
            for (int v4 = 0; v4 < 8; v4++) {
                uint4 u = src[v4];
                dh[v4*4+0] = (unsigned short)(u.x >> 16); dl[v4*4+0] = (unsigned short)u.x;
                dh[v4*4+1] = (unsigned short)(u.y >> 16); dl[v4*4+1] = (unsigned short)u.y;
                dh[v4*4+2] = (unsigned short)(u.z >> 16); dl[v4*4+2] = (unsigned short)u.z;
                dh[v4*4+3] = (unsigned short)(u.w >> 16); dl[v4*4+3] = (unsigned short)u.w;
            }
        }
        __syncthreads();

        // ---- chunks 1 (buf1, k 256-511) and 2 (buf0, k 512-767) ----
        if (w < 12) {
            #pragma unroll
            for (int c = 1; c < 3; c++) {
                const unsigned short* UhB = (c == 1) ? Uh1 : Uh0;
                const unsigned short* UlB = (c == 1) ? Ul1 : Ul0;
                const __nv_bfloat16* Ah = (const __nv_bfloat16*)(UhB + btile * 16 * USTRIDE);
                const __nv_bfloat16* Al = (const __nv_bfloat16*)(UlB + btile * 16 * USTRIDE);
                const __nv_bfloat16* Bh = (const __nv_bfloat16*)(Wh + ntile * 16 * WSTRIDE + c * 256);
                const __nv_bfloat16* Bl = (const __nv_bfloat16*)(Wl + ntile * 16 * WSTRIDE + c * 256);
                #pragma unroll
                for (int ks = kh * 8; ks < kh * 8 + 8; ks++) {
                    wmma::load_matrix_sync(fa_h, Ah + ks * 16, USTRIDE);
                    wmma::load_matrix_sync(fa_l, Al + ks * 16, USTRIDE);
                    wmma::load_matrix_sync(fb_h, Bh + ks * 16, WSTRIDE);
                    wmma::load_matrix_sync(fb_l, Bl + ks * 16, WSTRIDE);
                    wmma::mma_sync(facc, fa_h, fb_h, facc);
                    wmma::mma_sync(facc, fa_h, fb_l, facc);
                    wmma::mma_sync(facc, fa_l, fb_h, facc);
                }
            }
        }

        // ---- combine the 2-way K split ----
        if (w < 12 && kh == 1)
            wmma::store_matrix_sync(Dred + tau * 256, facc, 16, wmma::mem_row_major);
        __syncthreads();
        if (w < 12 && kh == 0) {
            wmma::load_matrix_sync(fc2, Dred + tau * 256, 16, wmma::mem_row_major);
            #pragma unroll
            for (int i = 0; i < facc.num_elements; i++) facc.x[i] += fc2.x[i];
            wmma::store_matrix_sync(Dred + tau * 256, facc, 16, wmma::mem_row_major);
        }
        __syncthreads();

        // ---- gates + h update (one output element per thread) ----
        {
            float dr  = Dred[(gbt * 3 + 0) * 256 + gbl * 16 + jj];
            float dz  = Dred[(gbt * 3 + 1) * 256 + gbl * 16 + jj];
            float dhn = Dred[(gbt * 3 + 2) * 256 + gbl * 16 + jj];
            float dxn = Dxn[(gbt * 2 + 0) * 256 + gbl * 16 + jj]
                      + Dxn[(gbt * 2 + 1) * 256 + gbl * 16 + jj];
            float r = sigm(dr + bias_r);
            float z = sigm(dz + bias_z);
            float n = tanhf(dxn + bias_xn + r * (dhn + bias_hn));
            const int gidx = (b0 + bb) * HH + j0 + jj;
            float hold = g_h[rp][gidx];
            float hv = n + z * (hold - n);
            g_h[wp][gidx]  = hv;
            g_hs[wp][gidx] = pack_bf16x2(hv);
            if (t == TT - 1) out[gidx] = hv;
        }

        __syncthreads();

        // ---- arrive ----
        if (tid == 0) {
            __threadfence();
            if (atomicAdd(&g_count, 1u) == NCTA - 1u) {
                g_count = 0;
                __threadfence();
                *((volatile unsigned*)&g_phase) =
                    *((volatile unsigned*)&g_phase) + 1u;
            }
        }
    }
}

extern "C" void kernel_launch(void* const* d_in, const int* in_sizes, int n_in,
                              void* d_out, int out_size) {
    (void)in_sizes; (void)n_in; (void)out_size;
    cudaFuncSetAttribute(gru_persistent_kernel,
                         cudaFuncAttributeMaxDynamicSharedMemorySize, SMEM_BYTES);
    gru_persistent_kernel<<<NCTA, NTHR, SMEM_BYTES>>>(
        (const float*)d_in[0],
        (const float*)d_in[1],
        (const float*)d_in[2],
        (const float*)d_in[3],
        (const float*)d_in[4],
        (float*)d_out);
}

// round 10
// speedup vs baseline: 2.5459x; 1.2466x over previous
#include <cuda_runtime.h>
#include <cuda_bf16.h>
#include <mma.h>
#include <math.h>

// GRU: B=128, T=512, I=256, H=512. out = final h [1,128,512] fp32.
// Persistent kernel, 128 CTAs (4 batch x 32 j slices), wmma bf16 hi/lo split
// (3-product fp32 emulation). x and h are kept as separate bf16 hi/lo u16
// planes in global, so SMEM staging is pure uint4 copies. No K-combine phase:
// kh partials summed in the gate phase.

using namespace nvcuda;

#define BATCH 128
#define TT    512
#define II    256
#define HH    512
#define GB    4
#define GJ    32
#define BC    32
#define JC    16
#define NCTA  (GB*GJ)
#define NTHR  512

#define WSTRIDE 776     // u16 per W row (768+8): 16B-aligned rows, bank offset 4
#define USTRIDE 264     // u16 per U row (256+8)

// SMEM byte offsets
#define SM_WH   0
#define SM_WL   (SM_WH  + 48*WSTRIDE*2)
#define SM_UH1  (SM_WL  + 48*WSTRIDE*2)        // buf1 = h[0:256]
#define SM_UL1  (SM_UH1 + 32*USTRIDE*2)
#define SM_UH0  (SM_UL1 + 32*USTRIDE*2)        // buf0 = x / h[256:512]
#define SM_UL0  (SM_UH0 + 32*USTRIDE*2)
#define SM_DRED (SM_UL0 + 32*USTRIDE*2)        // 12 tiles * 256 f32
#define SM_DXN  (SM_DRED + 12*256*4)           // 2 tiles * 256 f32
#define SM_BS   (SM_DXN + 2*256*4)             // 64 f32
#define SMEM_BYTES (SM_BS + 256)               // 231168

__device__ float          g_h  [2][BATCH*HH];
__device__ unsigned short g_hsh[2][BATCH*HH];
__device__ unsigned short g_hsl[2][BATCH*HH];
__device__ unsigned short g_xh [(size_t)BATCH*TT*II];
__device__ unsigned short g_xl [(size_t)BATCH*TT*II];
__device__ unsigned int   g_count = 0;
__device__ unsigned int   g_phase = 0;

__device__ __forceinline__ float sigm(float x) {
    return 1.0f / (1.0f + __expf(-x));
}

__device__ __forceinline__ void grid_sync_full() {
    __syncthreads();
    if (threadIdx.x == 0) {
        __threadfence();
        unsigned gen = *((volatile unsigned*)&g_phase);
        if (atomicAdd(&g_count, 1u) == NCTA - 1u) {
            g_count = 0;
            __threadfence();
            *((volatile unsigned*)&g_phase) = gen + 1u;
        } else {
            while (*((volatile unsigned*)&g_phase) == gen) { __nanosleep(32); }
        }
        __threadfence();
    }
    __syncthreads();
}

extern "C" __global__ void __launch_bounds__(NTHR, 1)
gru_persistent_kernel(const float* __restrict__ x,      // [B, T, I]
                      const float* __restrict__ W_ih,   // [3H, I]
                      const float* __restrict__ W_hh,   // [3H, H]
                      const float* __restrict__ b_ih,   // [3H]
                      const float* __restrict__ b_hh,   // [3H]
                      float* __restrict__ out)          // [1, B, H]
{
    extern __shared__ char smem[];
    unsigned short* Wh  = (unsigned short*)(smem + SM_WH);
    unsigned short* Wl  = (unsigned short*)(smem + SM_WL);
    unsigned short* Uh1 = (unsigned short*)(smem + SM_UH1);
    unsigned short* Ul1 = (unsigned short*)(smem + SM_UL1);
    unsigned short* Uh0 = (unsigned short*)(smem + SM_UH0);
    unsigned short* Ul0 = (unsigned short*)(smem + SM_UL0);
    float* Dred = (float*)(smem + SM_DRED);
    float* Dxn  = (float*)(smem + SM_DXN);
    float* B_s  = (float*)(smem + SM_BS);

    const int tid = threadIdx.x;
    const int bx  = blockIdx.x;
    const int gb  = bx & (GB - 1);
    const int gj  = bx >> 2;
    const int b0  = gb * BC;
    const int j0  = gj * JC;

    // relative-phase base (all CTAs read before the init barrier flips it)
    unsigned base = 0;
    if (tid == 0) base = *((volatile unsigned*)&g_phase);

    // ---- one-time: W tile as bf16 hi/lo (rows 0-15 r, 16-31 z, 32-47 n) ----
    for (int idx = tid; idx < 48 * 768; idx += NTHR) {
        int row = idx / 768;
        int col = idx - row * 768;
        int G;
        if (row < 16)      G = j0 + row;
        else if (row < 32) G = 512 + j0 + (row - 16);
        else               G = 1024 + j0 + (row - 32);
        float v = (col < II) ? W_ih[G * II + col] : W_hh[G * HH + (col - II)];
        __nv_bfloat16 hi = __float2bfloat16(v);
        __nv_bfloat16 lo = __float2bfloat16(v - __bfloat162float(hi));
        Wh[row * WSTRIDE + col] = __bfloat16_as_ushort(hi);
        Wl[row * WSTRIDE + col] = __bfloat16_as_ushort(lo);
    }
    if (tid < 64) {
        int i = tid & 15;
        float v;
        if (tid < 16)      v = b_ih[j0 + i]       + b_hh[j0 + i];        // r
        else if (tid < 32) v = b_ih[512 + j0 + i] + b_hh[512 + j0 + i];  // z
        else if (tid < 48) v = b_ih[1024 + j0 + i];                      // xn
        else               v = b_hh[1024 + j0 + i];                      // hn
        B_s[tid] = v;
    }

    // ---- pre-phase: split x into hi/lo planes; zero h0 ----
    {
        const size_t total = (size_t)BATCH * TT * II;
        for (size_t i = (size_t)(bx * NTHR + tid) * 8; i < total;
             i += (size_t)NCTA * NTHR * 8) {
            float4 v0 = *(const float4*)(x + i);
            float4 v1 = *(const float4*)(x + i + 4);
            float vv[8] = {v0.x, v0.y, v0.z, v0.w, v1.x, v1.y, v1.z, v1.w};
            unsigned hs[8], ls[8];
            #pragma unroll
            for (int j = 0; j < 8; j++) {
                __nv_bfloat16 hi = __float2bfloat16(vv[j]);
                __nv_bfloat16 lo = __float2bfloat16(vv[j] - __bfloat162float(hi));
                hs[j] = __bfloat16_as_ushort(hi);
                ls[j] = __bfloat16_as_ushort(lo);
            }
            uint4 ph, pl;
            ph.x = hs[0] | (hs[1] << 16); ph.y = hs[2] | (hs[3] << 16);
            ph.z = hs[4] | (hs[5] << 16); ph.w = hs[6] | (hs[7] << 16);
            pl.x = ls[0] | (ls[1] << 16); pl.y = ls[2] | (ls[3] << 16);
            pl.z = ls[4] | (ls[5] << 16); pl.w = ls[6] | (ls[7] << 16);
            *(uint4*)(g_xh + i) = ph;
            *(uint4*)(g_xl + i) = pl;
        }
        for (int i = bx * NTHR + tid; i < BATCH * HH; i += NCTA * NTHR) {
            g_h[0][i] = 0.0f;
            g_hsh[0][i] = 0;
            g_hsl[0][i] = 0;
        }
    }

    grid_sync_full();   // phase -> base+1

    // mma warp roles: w<12 -> (btile, ntile, kh)
    const int w     = tid >> 5;
    const int kh    = w & 1;
    const int tau   = w >> 1;          // 0..5 (valid for w<12)
    const int btile = tau / 3;
    const int ntile = tau % 3;

    wmma::fragment<wmma::matrix_a, 16, 16, 16, __nv_bfloat16, wmma::row_major> fa_h, fa_l;
    wmma::fragment<wmma::matrix_b, 16, 16, 16, __nv_bfloat16, wmma::col_major> fb_h, fb_l;
    wmma::fragment<wmma::accumulator, 16, 16, 16, float> facc;

    // staging indices
    const int srow = tid >> 4;          // 0..31
    const int sk16 = (tid & 15) * 16;   // x staging: 16 u16 = 32B per plane
    const int sk32 = (tid & 15) * 32;   // h staging: 32 u16 = 64B per plane

    // gate-phase mapping (one (b, j) element per thread)
    const int jj  = tid & 15;
    const int bb  = tid >> 4;           // 0..31
    const int gbt = bb >> 4;
    const int gbl = bb & 15;
    const float bias_r  = B_s[jj];
    const float bias_z  = B_s[16 + jj];
    const float bias_xn = B_s[32 + jj];
    const float bias_hn = B_s[48 + jj];

    for (int t = 0; t < TT; t++) {
        const int rp = t & 1;
        const int wp = rp ^ 1;

        // ---- stage x(t): plane copy into buf0 ----
        {
            const size_t off = ((size_t)(b0 + srow) * TT + t) * II + sk16;
            const uint4* sh = (const uint4*)(g_xh + off);
            const uint4* sl = (const uint4*)(g_xl + off);
            uint4* dh = (uint4*)(Uh0 + srow * USTRIDE + sk16);
            uint4* dl = (uint4*)(Ul0 + srow * USTRIDE + sk16);
            dh[0] = sh[0]; dh[1] = sh[1];
            dl[0] = sl[0]; dl[1] = sl[1];
        }
        __syncthreads();

        // ---- chunk 0: x projection (independent of peers' h) ----
        if (w < 12) {
            wmma::fill_fragment(facc, 0.0f);
            const __nv_bfloat16* Ah = (const __nv_bfloat16*)(Uh0 + btile * 16 * USTRIDE);
            const __nv_bfloat16* Al = (const __nv_bfloat16*)(Ul0 + btile * 16 * USTRIDE);
            const __nv_bfloat16* Bh = (const __nv_bfloat16*)(Wh + ntile * 16 * WSTRIDE);
            const __nv_bfloat16* Bl = (const __nv_bfloat16*)(Wl + ntile * 16 * WSTRIDE);
            if (ntile < 2) {
                #pragma unroll
                for (int ks = kh * 8; ks < kh * 8 + 8; ks++) {
                    wmma::load_matrix_sync(fa_h, Ah + ks * 16, USTRIDE);
                    wmma::load_matrix_sync(fa_l, Al + ks * 16, USTRIDE);
                    wmma::load_matrix_sync(fb_h, Bh + ks * 16, WSTRIDE);
                    wmma::load_matrix_sync(fb_l, Bl + ks * 16, WSTRIDE);
                    wmma::mma_sync(facc, fa_h, fb_h, facc);
                    wmma::mma_sync(facc, fa_h, fb_l, facc);
                    wmma::mma_sync(facc, fa_l, fb_h, facc);
                }
            } else if (kh == 0) {   // ntile==2: one warp does all 16 ks, stores xn
                #pragma unroll
                for (int ks = 0; ks < 16; ks++) {
                    wmma::load_matrix_sync(fa_h, Ah + ks * 16, USTRIDE);
                    wmma::load_matrix_sync(fa_l, Al + ks * 16, USTRIDE);
                    wmma::load_matrix_sync(fb_h, Bh + ks * 16, WSTRIDE);
                    wmma::load_matrix_sync(fb_l, Bl + ks * 16, WSTRIDE);
                    wmma::mma_sync(facc, fa_h, fb_h, facc);
                    wmma::mma_sync(facc, fa_h, fb_l, facc);
                    wmma::mma_sync(facc, fa_l, fb_h, facc);
                }
                wmma::store_matrix_sync(Dxn + btile * 256, facc, 16, wmma::mem_row_major);
                wmma::fill_fragment(facc, 0.0f);
            }
        }

        // ---- wait for peers' h(t-1) (hidden behind x-stage + chunk-0 mma) ----
        if (tid == 0) {
            while ((unsigned)(*((volatile unsigned*)&g_phase) - base) < (unsigned)(t + 1)) {
                __nanosleep(32);
            }
            __threadfence();
        }
        __syncthreads();

        // ---- stage h planes: h[0:256]->buf1, h[256:512]->buf0 ----
        {
            const int goff = (b0 + srow) * HH + sk32;
            const uint4* sh = (const uint4*)(g_hsh[rp] + goff);
            const uint4* sl = (const uint4*)(g_hsl[rp] + goff);
            uint4 *dh, *dl;
            if (sk32 < 256) {
                dh = (uint4*)(Uh1 + srow * USTRIDE + sk32);
                dl = (uint4*)(Ul1 + srow * USTRIDE + sk32);
            } else {
                dh = (uint4*)(Uh0 + srow * USTRIDE + (sk32 - 256));
                dl = (uint4*)(Ul0 + srow * USTRIDE + (sk32 - 256));
            }
            dh[0] = sh[0]; dh[1] = sh[1]; dh[2] = sh[2]; dh[3] = sh[3];
            dl[0] = sl[0]; dl[1] = sl[1]; dl[2] = sl[2]; dl[3] = sl[3];
        }
        __syncthreads();

        // ---- chunks 1 (buf1) + 2 (buf0): h projection ----
        if (w < 12) {
            #pragma unroll
            for (int c = 1; c < 3; c++) {
                const unsigned short* UhB = (c == 1) ? Uh1 : Uh0;
                const unsigned short* UlB = (c == 1) ? Ul1 : Ul0;
                const __nv_bfloat16* Ah = (const __nv_bfloat16*)(UhB + btile * 16 * USTRIDE);
                const __nv_bfloat16* Al = (const __nv_bfloat16*)(UlB + btile * 16 * USTRIDE);
                const __nv_bfloat16* Bh = (const __nv_bfloat16*)(Wh + ntile * 16 * WSTRIDE + c * 256);
                const __nv_bfloat16* Bl = (const __nv_bfloat16*)(Wl + ntile * 16 * WSTRIDE + c * 256);
                #pragma unroll
                for (int ks = kh * 8; ks < kh * 8 + 8; ks++) {
                    wmma::load_matrix_sync(fa_h, Ah + ks * 16, USTRIDE);
                    wmma::load_matrix_sync(fa_l, Al + ks * 16, USTRIDE);
                    wmma::load_matrix_sync(fb_h, Bh + ks * 16, WSTRIDE);
                    wmma::load_matrix_sync(fb_l, Bl + ks * 16, WSTRIDE);
                    wmma::mma_sync(facc, fa_h, fb_h, facc);
                    wmma::mma_sync(facc, fa_h, fb_l, facc);
                    wmma::mma_sync(facc, fa_l, fb_h, facc);
                }
            }
            // store partial (both kh); gate phase sums
            wmma::store_matrix_sync(Dred + ((btile * 3 + ntile) * 2 + kh) * 256,
                                    facc, 16, wmma::mem_row_major);
        }
        __syncthreads();

        // ---- gates + h update ----
        {
            const int off = gbl * 16 + jj;
            float dr  = Dred[((gbt * 3 + 0) * 2 + 0) * 256 + off]
                      + Dred[((gbt * 3 + 0) * 2 + 1) * 256 + off];
            float dz  = Dred[((gbt * 3 + 1) * 2 + 0) * 256 + off]
                      + Dred[((gbt * 3 + 1) * 2 + 1) * 256 + off];
            float dhn = Dred[((gbt * 3 + 2) * 2 + 0) * 256 + off]
                      + Dred[((gbt * 3 + 2) * 2 + 1) * 256 + off];
            float dxn = Dxn[gbt * 256 + off];
            float r = sigm(dr + bias_r);
            float z = sigm(dz + bias_z);
            float n = tanhf(dxn + bias_xn + r * (dhn + bias_hn));
            const int gidx = (b0 + bb) * HH + j0 + jj;
            float hold = g_h[rp][gidx];
            float hv = n + z * (hold - n);
            g_h[wp][gidx] = hv;
            __nv_bfloat16 hi = __float2bfloat16(hv);
            __nv_bfloat16 lo = __float2bfloat16(hv - __bfloat162float(hi));
            g_hsh[wp][gidx] = __bfloat16_as_ushort(hi);
            g_hsl[wp][gidx] = __bfloat16_as_ushort(lo);
            if (t == TT - 1) out[gidx] = hv;
        }

        __syncthreads();

        // ---- arrive ----
        if (tid == 0) {
            __threadfence();
            if (atomicAdd(&g_count, 1u) == NCTA - 1u) {
                g_count = 0;
                __threadfence();
                *((volatile unsigned*)&g_phase) =
                    *((volatile unsigned*)&g_phase) + 1u;
            }
        }
    }
}

extern "C" void kernel_launch(void* const* d_in, const int* in_sizes, int n_in,
                              void* d_out, int out_size) {
    (void)in_sizes; (void)n_in; (void)out_size;
    cudaFuncSetAttribute(gru_persistent_kernel,
                         cudaFuncAttributeMaxDynamicSharedMemorySize, SMEM_BYTES);
    gru_persistent_kernel<<<NCTA, NTHR, SMEM_BYTES>>>(
        (const float*)d_in[0],
        (const float*)d_in[1],
        (const float*)d_in[2],
        (const float*)d_in[3],
        (const float*)d_in[4],
        (float*)d_out);
}